// round 15
// baseline (speedup 1.0000x reference)
#include <cuda_runtime.h>
#include <cuda_bf16.h>
#include <cstdint>

// ---------------------------------------------------------------------------
// Quaternion Hamilton-product tables
// ---------------------------------------------------------------------------
__constant__ int   c_cmp[16] = {0,1,2,3,  1,0,3,2,  2,3,0,1,  3,2,1,0};
__constant__ float c_sgn[16] = {1.f,-1.f,-1.f,-1.f,
                                1.f, 1.f, 1.f,-1.f,
                                1.f,-1.f, 1.f, 1.f,
                                1.f, 1.f,-1.f, 1.f};

// ---------------------------------------------------------------------------
// Scratch (device globals)
// ---------------------------------------------------------------------------
__device__ float g_buf1[4*512*1024];
__device__ float g_buf2[4*768*1024];
__device__ float g_buf3[4*256*1024];
__device__ __align__(16) __nv_bfloat16 g_xh0[4*512*1024];
__device__ __align__(16) __nv_bfloat16 g_xl0[4*512*1024];
__device__ __align__(16) __nv_bfloat16 g_xh1[4*512*1024];
__device__ __align__(16) __nv_bfloat16 g_xl1[4*512*1024];
__device__ __align__(16) __nv_bfloat16 g_Wh[1048576];
__device__ __align__(16) __nv_bfloat16 g_Wl[1048576];

#define OFF_W1 0
#define OFF_WQ (OFF_W1 + 512*512)
#define OFF_WP (OFF_WQ + 768*256)
#define OFF_F1 (OFF_WP + 256*256)
#define OFF_F2 (OFF_F1 + 512*256)
#define OFF_C2 (OFF_F2 + 256*512)

__device__ __forceinline__ void splitf(float v, __nv_bfloat16& h, __nv_bfloat16& l) {
    h = __float2bfloat16(v);
    l = __float2bfloat16(v - __bfloat162float(h));
}

// Paired split via cvt.rn.bf16x2 — bit-identical to two splitf calls.
__device__ __forceinline__ uint32_t cvt2(float hi, float lo) {
    uint32_t d;
    asm("cvt.rn.bf16x2.f32 %0, %1, %2;" : "=r"(d) : "f"(hi), "f"(lo));
    return d;
}
__device__ __forceinline__ void pack2(float x, float y, uint32_t& h, uint32_t& l) {
    h = cvt2(y, x);
    float hx = __uint_as_float(h << 16);
    float hy = __uint_as_float(h & 0xFFFF0000u);
    l = cvt2(y - hy, x - hx);
}

// ---------------------------------------------------------------------------
// Dummy kernel: shifts the ncu capture slot onto the cv1 GEMM.
// ---------------------------------------------------------------------------
__global__ void dummy_kernel() {}

// ---------------------------------------------------------------------------
// Fused expansion: quaternion weights -> dense bf16 hi/lo GEMM weights
// ---------------------------------------------------------------------------
__global__ void expand_all_kernel(const float* __restrict__ w0, const float* __restrict__ w1,
                                  const float* __restrict__ w2, const float* __restrict__ w3,
                                  const float* __restrict__ w4, const float* __restrict__ w5,
                                  __nv_bfloat16* __restrict__ Wh, __nv_bfloat16* __restrict__ Wl) {
    const int Couts[6] = {128,192,64,128,64,128};
    const int Cins [6] = {128, 64,64, 64,128,128};
    const int offs [6] = {OFF_W1,OFF_WQ,OFF_WP,OFF_F1,OFF_F2,OFF_C2};
    const float* srcs[6] = {w0,w1,w2,w3,w4,w5};
    int q = blockIdx.y;
    int Cout = Couts[q], Cin = Cins[q];
    const float* w = srcs[q];
    int off = offs[q];
    int total = 16 * Cout * Cin;
    for (int i = blockIdx.x * blockDim.x + threadIdx.x; i < total;
         i += gridDim.x * blockDim.x) {
        int s = i & 3, t = (i >> 2) & 3;
        int rest = i >> 4;
        int ci = rest % Cin, co = rest / Cin;
        float val = c_sgn[t*4 + s] * w[c_cmp[t*4 + s] * Cout * Cin + co * Cin + ci];
        __nv_bfloat16 h, l;
        splitf(val, h, l);
        int idx = off + (co*4 + t) * (4*Cin) + ci*4 + s;
        Wh[idx] = h;
        Wl[idx] = l;
    }
}

// ---------------------------------------------------------------------------
// Plain fp32 -> bf16 hi/lo split (network input x)
// ---------------------------------------------------------------------------
__global__ __launch_bounds__(256) void split_x_kernel(const float* __restrict__ X,
                                                      __nv_bfloat16* __restrict__ H,
                                                      __nv_bfloat16* __restrict__ L) {
    int i = blockIdx.x * 256 + threadIdx.x;
    float4 v = ((const float4*)X)[i];
    uint32_t h01, l01, h23, l23;
    pack2(v.x, v.y, h01, l01);
    pack2(v.z, v.w, h23, l23);
    *(uint2*)(H + (long)i * 4) = make_uint2(h01, h23);
    *(uint2*)(L + (long)i * 4) = make_uint2(l01, l23);
}

// ---------------------------------------------------------------------------
// mma / ldmatrix helpers
// ---------------------------------------------------------------------------
__device__ __forceinline__ void mma16816(float* d, uint32_t a0, uint32_t a1,
                                         uint32_t a2, uint32_t a3,
                                         uint32_t b0, uint32_t b1) {
    asm volatile(
        "mma.sync.aligned.m16n8k16.row.col.f32.bf16.bf16.f32 "
        "{%0,%1,%2,%3}, {%4,%5,%6,%7}, {%8,%9}, {%0,%1,%2,%3};"
        : "+f"(d[0]), "+f"(d[1]), "+f"(d[2]), "+f"(d[3])
        : "r"(a0), "r"(a1), "r"(a2), "r"(a3), "r"(b0), "r"(b1));
}
__device__ __forceinline__ void ldsm4(uint32_t& r0, uint32_t& r1, uint32_t& r2,
                                      uint32_t& r3, uint32_t addr) {
    asm volatile("ldmatrix.sync.aligned.m8n8.x4.shared.b16 {%0,%1,%2,%3}, [%4];"
                 : "=r"(r0), "=r"(r1), "=r"(r2), "=r"(r3) : "r"(addr));
}
__device__ __forceinline__ void ldsm4t(uint32_t& r0, uint32_t& r1, uint32_t& r2,
                                       uint32_t& r3, uint32_t addr) {
    asm volatile("ldmatrix.sync.aligned.m8n8.x4.trans.shared.b16 {%0,%1,%2,%3}, [%4];"
                 : "=r"(r0), "=r"(r1), "=r"(r2), "=r"(r3) : "r"(addr));
}

// ---------------------------------------------------------------------------
// HMMA bf16-split GEMM (exact R10/R14 — untouched)
// ---------------------------------------------------------------------------
#define APITCH 40
#define BPITCH 136
#define A_PLANE (64*APITCH)
#define B_PLANE (32*BPITCH)
#define GBUF (2*A_PLANE + 2*B_PLANE)
#define GEMM_SMEM (2*GBUF*2)

__global__ __launch_bounds__(128) void mma_gemm_kernel(
    const __nv_bfloat16* __restrict__ Wh, const __nv_bfloat16* __restrict__ Wl,
    const __nv_bfloat16* __restrict__ Xh, const __nv_bfloat16* __restrict__ Xl,
    float* __restrict__ Y, const float* __restrict__ bias,
    int M, int K, long sX, long sY)
{
    extern __shared__ __nv_bfloat16 smd[];
    const uint32_t smem_base = (uint32_t)__cvta_generic_to_shared(smd);

    const int tid = threadIdx.x;
    const int wid = tid >> 5, lane = tid & 31;
    const int wm = wid & 1, wn = wid >> 1;
    const int g = lane >> 2, tg = lane & 3;
    const int mo = blockIdx.y * 64, no = blockIdx.x * 128;
    const __nv_bfloat16* Xhb = Xh + blockIdx.z * sX;
    const __nv_bfloat16* Xlb = Xl + blockIdx.z * sX;
    float* Yb = Y + blockIdx.z * sY;

    const int am = tid >> 1, ak = (tid & 1) * 16;
    const int bcol = (tid & 31) * 4;
    const int bk0 = (tid >> 5) * 2;

    float acc[2][8][4] = {};
    const int nch = K >> 5;

    uint4 awh[2], awl[2];
    uint2 bh[4][2], bl[4][2];

#define LOAD_REGS(kt)                                                            \
    {                                                                            \
        const __nv_bfloat16* Ah = Wh + (long)(mo + am) * K + (kt) + ak;          \
        const __nv_bfloat16* Al = Wl + (long)(mo + am) * K + (kt) + ak;          \
        awh[0] = *(const uint4*)Ah; awh[1] = *(const uint4*)(Ah + 8);            \
        awl[0] = *(const uint4*)Al; awl[1] = *(const uint4*)(Al + 8);            \
        _Pragma("unroll")                                                        \
        for (int I = 0; I < 4; I++) {                                            \
            int kr = (kt) + bk0 + 8 * I;                                         \
            const __nv_bfloat16* Bh = Xhb + (long)kr * 1024 + no + bcol;         \
            const __nv_bfloat16* Bl = Xlb + (long)kr * 1024 + no + bcol;         \
            bh[I][0] = *(const uint2*)Bh; bh[I][1] = *(const uint2*)(Bh + 1024); \
            bl[I][0] = *(const uint2*)Bl; bl[I][1] = *(const uint2*)(Bl + 1024); \
        }                                                                        \
    }

#define STORE_SMEM(buf)                                                          \
    {                                                                            \
        __nv_bfloat16* base = smd + (buf) * GBUF;                                \
        uint32_t* dH = (uint32_t*)(base + am * APITCH + ak);                     \
        uint32_t* dL = (uint32_t*)(base + A_PLANE + am * APITCH + ak);           \
        *(uint4*)dH = awh[0]; *(uint4*)(dH + 4) = awh[1];                        \
        *(uint4*)dL = awl[0]; *(uint4*)(dL + 4) = awl[1];                        \
        __nv_bfloat16* BH = base + 2 * A_PLANE;                                  \
        __nv_bfloat16* BL = base + 2 * A_PLANE + B_PLANE;                        \
        _Pragma("unroll")                                                        \
        for (int I = 0; I < 4; I++) {                                            \
            int kr = bk0 + 8 * I;                                                \
            *(uint2*)(BH + kr * BPITCH + bcol)       = bh[I][0];                 \
            *(uint2*)(BH + (kr + 1) * BPITCH + bcol) = bh[I][1];                 \
            *(uint2*)(BL + kr * BPITCH + bcol)       = bl[I][0];                 \
            *(uint2*)(BL + (kr + 1) * BPITCH + bcol) = bl[I][1];                 \
        }                                                                        \
    }

    LOAD_REGS(0);
    STORE_SMEM(0);
    if (nch > 1) LOAD_REGS(32);
    __syncthreads();

    const int a_row_l = lane & 15;
    const int a_khalf = (lane >> 4) * 8;
    const int b_krow  = (lane & 7) + 8 * ((lane >> 3) & 1);
    const int b_nhalf = (lane >> 4) * 8;

    for (int ch = 0; ch < nch; ch++) {
        if (ch + 1 < nch) STORE_SMEM((ch + 1) & 1);
        if (ch + 2 < nch) LOAD_REGS((ch + 2) * 32);

        uint32_t bufu = (uint32_t)((ch & 1) * GBUF) * 2u;
        uint32_t AH = smem_base + bufu;
        uint32_t ALo = AH + A_PLANE * 2;
        uint32_t BH = AH + 4 * A_PLANE;
        uint32_t BLo = BH + B_PLANE * 2;

#pragma unroll
        for (int k0 = 0; k0 < 32; k0 += 16) {
            uint32_t ah[2][4], al[2][4];
#pragma unroll
            for (int mt = 0; mt < 2; mt++) {
                int rowb = wm * 32 + mt * 16;
                uint32_t off = (uint32_t)((rowb + a_row_l) * APITCH + k0 + a_khalf) * 2u;
                ldsm4(ah[mt][0], ah[mt][1], ah[mt][2], ah[mt][3], AH + off);
                ldsm4(al[mt][0], al[mt][1], al[mt][2], al[mt][3], ALo + off);
            }
#pragma unroll
            for (int ntp = 0; ntp < 4; ntp++) {
                int nbase = wn * 64 + ntp * 16;
                uint32_t off = (uint32_t)((k0 + b_krow) * BPITCH + nbase + b_nhalf) * 2u;
                uint32_t bh0, bh1, bh2, bh3, bl0, bl1, bl2, bl3;
                ldsm4t(bh0, bh1, bh2, bh3, BH + off);
                ldsm4t(bl0, bl1, bl2, bl3, BLo + off);
#pragma unroll
                for (int mt = 0; mt < 2; mt++) {
                    float* d0 = acc[mt][ntp * 2];
                    float* d1 = acc[mt][ntp * 2 + 1];
                    mma16816(d0, ah[mt][0], ah[mt][1], ah[mt][2], ah[mt][3], bh0, bh1);
                    mma16816(d0, al[mt][0], al[mt][1], al[mt][2], al[mt][3], bh0, bh1);
                    mma16816(d0, ah[mt][0], ah[mt][1], ah[mt][2], ah[mt][3], bl0, bl1);
                    mma16816(d1, ah[mt][0], ah[mt][1], ah[mt][2], ah[mt][3], bh2, bh3);
                    mma16816(d1, al[mt][0], al[mt][1], al[mt][2], al[mt][3], bh2, bh3);
                    mma16816(d1, ah[mt][0], ah[mt][1], ah[mt][2], ah[mt][3], bl2, bl3);
                }
            }
        }
        if (ch + 1 < nch) __syncthreads();
    }

#pragma unroll
    for (int mt = 0; mt < 2; mt++) {
        int r0 = mo + wm * 32 + mt * 16 + g;
        int r1 = r0 + 8;
        float bv0 = bias ? bias[r0] : 0.f;
        float bv1 = bias ? bias[r1] : 0.f;
#pragma unroll
        for (int nt = 0; nt < 8; nt++) {
            int c = no + wn * 64 + nt * 8 + 2 * tg;
            float* d = acc[mt][nt];
            *(float2*)(Yb + (long)r0 * 1024 + c) = make_float2(d[0] + bv0, d[1] + bv0);
            *(float2*)(Yb + (long)r1 * 1024 + c) = make_float2(d[2] + bv1, d[3] + bv1);
        }
    }
#undef LOAD_REGS
#undef STORE_SMEM
}

// ---------------------------------------------------------------------------
// Small-M GEMM variant: CTA tile 32m x 128n, 4 warps (warp tile 32x32),
// same staging scheme. Separate kernel -> zero register risk to main GEMM.
// Used for proj (M=256) and ffn2 (M=256): grid doubles to 256 CTAs.
// ---------------------------------------------------------------------------
#define A2_PLANE (32*APITCH)
#define G2BUF (2*A2_PLANE + 2*B_PLANE)
#define GEMM2_SMEM (2*G2BUF*2)

__global__ __launch_bounds__(128) void mma_gemm_m32(
    const __nv_bfloat16* __restrict__ Wh, const __nv_bfloat16* __restrict__ Wl,
    const __nv_bfloat16* __restrict__ Xh, const __nv_bfloat16* __restrict__ Xl,
    float* __restrict__ Y, const float* __restrict__ bias,
    int M, int K, long sX, long sY)
{
    extern __shared__ __nv_bfloat16 smd[];
    const uint32_t smem_base = (uint32_t)__cvta_generic_to_shared(smd);

    const int tid = threadIdx.x;
    const int wid = tid >> 5, lane = tid & 31;
    const int g = lane >> 2, tg = lane & 3;
    const int mo = blockIdx.y * 32, no = blockIdx.x * 128;
    const __nv_bfloat16* Xhb = Xh + blockIdx.z * sX;
    const __nv_bfloat16* Xlb = Xl + blockIdx.z * sX;
    float* Yb = Y + blockIdx.z * sY;

    const int am = tid >> 2, ak = (tid & 3) * 8;     // A: 32 rows x 32 k, 8 bf16/thread
    const int bcol = (tid & 31) * 4;
    const int bk0 = (tid >> 5) * 2;

    float acc[2][4][4] = {};
    const int nch = K >> 5;

    uint4 awh, awl;
    uint2 bh[4][2], bl[4][2];

#define LOAD_REGS2(kt)                                                           \
    {                                                                            \
        const __nv_bfloat16* Ah = Wh + (long)(mo + am) * K + (kt) + ak;          \
        const __nv_bfloat16* Al = Wl + (long)(mo + am) * K + (kt) + ak;          \
        awh = *(const uint4*)Ah;                                                 \
        awl = *(const uint4*)Al;                                                 \
        _Pragma("unroll")                                                        \
        for (int I = 0; I < 4; I++) {                                            \
            int kr = (kt) + bk0 + 8 * I;                                         \
            const __nv_bfloat16* Bh = Xhb + (long)kr * 1024 + no + bcol;         \
            const __nv_bfloat16* Bl = Xlb + (long)kr * 1024 + no + bcol;         \
            bh[I][0] = *(const uint2*)Bh; bh[I][1] = *(const uint2*)(Bh + 1024); \
            bl[I][0] = *(const uint2*)Bl; bl[I][1] = *(const uint2*)(Bl + 1024); \
        }                                                                        \
    }

#define STORE_SMEM2(buf)                                                         \
    {                                                                            \
        __nv_bfloat16* base = smd + (buf) * G2BUF;                               \
        *(uint4*)(base + am * APITCH + ak) = awh;                                \
        *(uint4*)(base + A2_PLANE + am * APITCH + ak) = awl;                     \
        __nv_bfloat16* BH = base + 2 * A2_PLANE;                                 \
        __nv_bfloat16* BL = base + 2 * A2_PLANE + B_PLANE;                       \
        _Pragma("unroll")                                                        \
        for (int I = 0; I < 4; I++) {                                            \
            int kr = bk0 + 8 * I;                                                \
            *(uint2*)(BH + kr * BPITCH + bcol)       = bh[I][0];                 \
            *(uint2*)(BH + (kr + 1) * BPITCH + bcol) = bh[I][1];                 \
            *(uint2*)(BL + kr * BPITCH + bcol)       = bl[I][0];                 \
            *(uint2*)(BL + (kr + 1) * BPITCH + bcol) = bl[I][1];                 \
        }                                                                        \
    }

    LOAD_REGS2(0);
    STORE_SMEM2(0);
    if (nch > 1) LOAD_REGS2(32);
    __syncthreads();

    const int a_row_l = lane & 15;
    const int a_khalf = (lane >> 4) * 8;
    const int b_krow  = (lane & 7) + 8 * ((lane >> 3) & 1);
    const int b_nhalf = (lane >> 4) * 8;

    for (int ch = 0; ch < nch; ch++) {
        if (ch + 1 < nch) STORE_SMEM2((ch + 1) & 1);
        if (ch + 2 < nch) LOAD_REGS2((ch + 2) * 32);

        uint32_t bufu = (uint32_t)((ch & 1) * G2BUF) * 2u;
        uint32_t AH = smem_base + bufu;
        uint32_t ALo = AH + A2_PLANE * 2;
        uint32_t BH = AH + 4 * A2_PLANE;
        uint32_t BLo = BH + B_PLANE * 2;

#pragma unroll
        for (int k0 = 0; k0 < 32; k0 += 16) {
            uint32_t ah[2][4], al[2][4];
#pragma unroll
            for (int mt = 0; mt < 2; mt++) {
                int rowb = mt * 16;
                uint32_t off = (uint32_t)((rowb + a_row_l) * APITCH + k0 + a_khalf) * 2u;
                ldsm4(ah[mt][0], ah[mt][1], ah[mt][2], ah[mt][3], AH + off);
                ldsm4(al[mt][0], al[mt][1], al[mt][2], al[mt][3], ALo + off);
            }
#pragma unroll
            for (int ntp = 0; ntp < 2; ntp++) {
                int nbase = wid * 32 + ntp * 16;
                uint32_t off = (uint32_t)((k0 + b_krow) * BPITCH + nbase + b_nhalf) * 2u;
                uint32_t bh0, bh1, bh2, bh3, bl0, bl1, bl2, bl3;
                ldsm4t(bh0, bh1, bh2, bh3, BH + off);
                ldsm4t(bl0, bl1, bl2, bl3, BLo + off);
#pragma unroll
                for (int mt = 0; mt < 2; mt++) {
                    float* d0 = acc[mt][ntp * 2];
                    float* d1 = acc[mt][ntp * 2 + 1];
                    mma16816(d0, ah[mt][0], ah[mt][1], ah[mt][2], ah[mt][3], bh0, bh1);
                    mma16816(d0, al[mt][0], al[mt][1], al[mt][2], al[mt][3], bh0, bh1);
                    mma16816(d0, ah[mt][0], ah[mt][1], ah[mt][2], ah[mt][3], bl0, bl1);
                    mma16816(d1, ah[mt][0], ah[mt][1], ah[mt][2], ah[mt][3], bh2, bh3);
                    mma16816(d1, al[mt][0], al[mt][1], al[mt][2], al[mt][3], bh2, bh3);
                    mma16816(d1, ah[mt][0], ah[mt][1], ah[mt][2], ah[mt][3], bl2, bl3);
                }
            }
        }
        if (ch + 1 < nch) __syncthreads();
    }

#pragma unroll
    for (int mt = 0; mt < 2; mt++) {
        int r0 = mo + mt * 16 + g;
        int r1 = r0 + 8;
        float bv0 = bias ? bias[r0] : 0.f;
        float bv1 = bias ? bias[r1] : 0.f;
#pragma unroll
        for (int nt = 0; nt < 4; nt++) {
            int c = no + wid * 32 + (nt >> 1) * 16 + (nt & 1) * 8 + 2 * tg;
            float* d = acc[mt][nt];
            *(float2*)(Yb + (long)r0 * 1024 + c) = make_float2(d[0] + bv0, d[1] + bv0);
            *(float2*)(Yb + (long)r1 * 1024 + c) = make_float2(d[2] + bv1, d[3] + bv1);
        }
    }
#undef LOAD_REGS2
#undef STORE_SMEM2
}

// ---------------------------------------------------------------------------
// Fused BN: stats + apply + bf16 split (R14, unchanged)
// ---------------------------------------------------------------------------
__global__ __launch_bounds__(256) void bn_fused_split(
    const float* __restrict__ X, __nv_bfloat16* __restrict__ H,
    __nv_bfloat16* __restrict__ L,
    const float* __restrict__ g, const float* __restrict__ be,
    long bsX, long bsP, int relu)
{
    int m = blockIdx.x, tid = threadIdx.x;
    float4 v[4];
    float s = 0.f, sq = 0.f;
#pragma unroll
    for (int b = 0; b < 4; b++) {
        v[b] = *(const float4*)(X + b * bsX + (long)m * 1024 + tid * 4);
        s  += v[b].x + v[b].y + v[b].z + v[b].w;
        sq += v[b].x*v[b].x + v[b].y*v[b].y + v[b].z*v[b].z + v[b].w*v[b].w;
    }
#pragma unroll
    for (int o = 16; o; o >>= 1) {
        s  += __shfl_xor_sync(0xffffffffu, s, o);
        sq += __shfl_xor_sync(0xffffffffu, sq, o);
    }
    __shared__ float ps[8], pq[8], bsc[1], bsh[1];
    if ((tid & 31) == 0) { ps[tid >> 5] = s; pq[tid >> 5] = sq; }
    __syncthreads();
    if (tid == 0) {
        s = 0.f; sq = 0.f;
#pragma unroll
        for (int i = 0; i < 8; i++) { s += ps[i]; sq += pq[i]; }
        float mean = s * (1.f / 4096.f);
        float var  = sq * (1.f / 4096.f) - mean * mean;
        float rstd = rsqrtf(var + 1e-5f);
        float sc = g[m] * rstd;
        bsc[0] = sc;
        bsh[0] = be[m] - mean * sc;
    }
    __syncthreads();
    float sc = bsc[0], sh = bsh[0];
#pragma unroll
    for (int b = 0; b < 4; b++) {
        float4 w = v[b];
        w.x = w.x * sc + sh; w.y = w.y * sc + sh;
        w.z = w.z * sc + sh; w.w = w.w * sc + sh;
        if (relu) {
            w.x = fmaxf(w.x, 0.f); w.y = fmaxf(w.y, 0.f);
            w.z = fmaxf(w.z, 0.f); w.w = fmaxf(w.w, 0.f);
        }
        uint32_t h01, l01, h23, l23;
        pack2(w.x, w.y, h01, l01);
        pack2(w.z, w.w, h23, l23);
        long o = (long)b * bsP + (long)m * 1024 + tid * 4;
        *(uint2*)(H + o) = make_uint2(h01, h23);
        *(uint2*)(L + o) = make_uint2(l01, l23);
    }
}

__global__ __launch_bounds__(256) void bn_fused_out(
    const float* __restrict__ X, float* __restrict__ Y,
    const float* __restrict__ g, const float* __restrict__ be,
    long bsX, long bsY, int relu)
{
    int m = blockIdx.x, tid = threadIdx.x;
    float4 v[4];
    float s = 0.f, sq = 0.f;
#pragma unroll
    for (int b = 0; b < 4; b++) {
        v[b] = *(const float4*)(X + b * bsX + (long)m * 1024 + tid * 4);
        s  += v[b].x + v[b].y + v[b].z + v[b].w;
        sq += v[b].x*v[b].x + v[b].y*v[b].y + v[b].z*v[b].z + v[b].w*v[b].w;
    }
#pragma unroll
    for (int o = 16; o; o >>= 1) {
        s  += __shfl_xor_sync(0xffffffffu, s, o);
        sq += __shfl_xor_sync(0xffffffffu, sq, o);
    }
    __shared__ float ps[8], pq[8], bsc[1], bsh[1];
    if ((tid & 31) == 0) { ps[tid >> 5] = s; pq[tid >> 5] = sq; }
    __syncthreads();
    if (tid == 0) {
        s = 0.f; sq = 0.f;
#pragma unroll
        for (int i = 0; i < 8; i++) { s += ps[i]; sq += pq[i]; }
        float mean = s * (1.f / 4096.f);
        float var  = sq * (1.f / 4096.f) - mean * mean;
        float rstd = rsqrtf(var + 1e-5f);
        float sc = g[m] * rstd;
        bsc[0] = sc;
        bsh[0] = be[m] - mean * sc;
    }
    __syncthreads();
    float sc = bsc[0], sh = bsh[0];
#pragma unroll
    for (int b = 0; b < 4; b++) {
        float4 w = v[b];
        w.x = w.x * sc + sh; w.y = w.y * sc + sh;
        w.z = w.z * sc + sh; w.w = w.w * sc + sh;
        if (relu) {
            w.x = fmaxf(w.x, 0.f); w.y = fmaxf(w.y, 0.f);
            w.z = fmaxf(w.z, 0.f); w.w = fmaxf(w.w, 0.f);
        }
        *(float4*)(Y + (long)b * bsY + (long)m * 1024 + tid * 4) = w;
    }
}

// ---------------------------------------------------------------------------
// Tensor-core flash attention (R14, unchanged)
// ---------------------------------------------------------------------------
#define QP 24
#define KP 24
#define VP 136

__global__ __launch_bounds__(256) void attn_kernel(const float* __restrict__ Yq,
                                                   float* __restrict__ O) {
    __shared__ __nv_bfloat16 QH[32*QP], QL[32*QP];
    __shared__ __nv_bfloat16 KH[128*KP], KL[128*KP];
    __shared__ __nv_bfloat16 VH[16*VP], VL[16*VP];
    __shared__ float redmax[4][32], redsum[4][32];
    __shared__ float Of[4][2][16][17];
    __shared__ float rsinv[32];

    int b = blockIdx.z, head = blockIdx.y >> 2, t = blockIdx.y & 3;
    int r0 = blockIdx.x * 32;
    const float* Yb = Yq + (long)b * 768 * 1024;
    int tid = threadIdx.x, lane = tid & 31, wid = tid >> 5;
    int wm = wid & 1, wn = wid >> 1;
    int g = lane >> 2, tg = lane & 3;

    for (int i = tid; i < 512; i += 256) {
        int dd = i >> 5, q = i & 31;
        float v = Yb[(head * 192 + dd * 4 + t) * 1024 + r0 + q];
        __nv_bfloat16 h, l; splitf(v, h, l);
        QH[q * QP + dd] = h;
        QL[q * QP + dd] = l;
    }
    __syncthreads();

    uint32_t qh[4], ql[4];
    {
        int r = wm * 16 + g;
        qh[0] = *(uint32_t*)&QH[r * QP + 2*tg];
        qh[1] = *(uint32_t*)&QH[(r + 8) * QP + 2*tg];
        qh[2] = *(uint32_t*)&QH[r * QP + 2*tg + 8];
        qh[3] = *(uint32_t*)&QH[(r + 8) * QP + 2*tg + 8];
        ql[0] = *(uint32_t*)&QL[r * QP + 2*tg];
        ql[1] = *(uint32_t*)&QL[(r + 8) * QP + 2*tg];
        ql[2] = *(uint32_t*)&QL[r * QP + 2*tg + 8];
        ql[3] = *(uint32_t*)&QL[(r + 8) * QP + 2*tg + 8];
    }

    float od[2][4] = {};
    float rm_lo = -1e30f, rm_hi = -1e30f, rs_lo = 0.f, rs_hi = 0.f;
    const float sc = 0.25f;
    const int rlo = wm * 16 + g, rhi = rlo + 8;

    for (int ch = 0; ch < 8; ch++) {
        __syncthreads();
        for (int i = tid; i < 2048; i += 256) {
            int dd = i >> 7, key = i & 127;
            float kval = Yb[(head * 192 + 64 + dd * 4 + t) * 1024 + ch * 128 + key];
            __nv_bfloat16 h, l; splitf(kval, h, l);
            KH[key * KP + dd] = h; KL[key * KP + dd] = l;
            float vval = Yb[(head * 192 + 128 + dd * 4 + t) * 1024 + ch * 128 + key];
            splitf(vval, h, l);
            VH[dd * VP + key] = h; VL[dd * VP + key] = l;
        }
        __syncthreads();

        float sacc[4][4] = {};
#pragma unroll
        for (int nt = 0; nt < 4; nt++) {
            int nb = wn * 32 + nt * 8 + g;
            uint32_t kb0 = *(uint32_t*)&KH[nb * KP + 2*tg];
            uint32_t kb1 = *(uint32_t*)&KH[nb * KP + 2*tg + 8];
            uint32_t kc0 = *(uint32_t*)&KL[nb * KP + 2*tg];
            uint32_t kc1 = *(uint32_t*)&KL[nb * KP + 2*tg + 8];
            mma16816(sacc[nt], qh[0], qh[1], qh[2], qh[3], kb0, kb1);
            mma16816(sacc[nt], ql[0], ql[1], ql[2], ql[3], kb0, kb1);
            mma16816(sacc[nt], qh[0], qh[1], qh[2], qh[3], kc0, kc1);
        }
        float mx_lo = -1e30f, mx_hi = -1e30f;
#pragma unroll
        for (int nt = 0; nt < 4; nt++) {
            sacc[nt][0] *= sc; sacc[nt][1] *= sc;
            sacc[nt][2] *= sc; sacc[nt][3] *= sc;
            mx_lo = fmaxf(mx_lo, fmaxf(sacc[nt][0], sacc[nt][1]));
            mx_hi = fmaxf(mx_hi, fmaxf(sacc[nt][2], sacc[nt][3]));
        }
        mx_lo = fmaxf(mx_lo, __shfl_xor_sync(0xffffffffu, mx_lo, 1));
        mx_lo = fmaxf(mx_lo, __shfl_xor_sync(0xffffffffu, mx_lo, 2));
        mx_hi = fmaxf(mx_hi, __shfl_xor_sync(0xffffffffu, mx_hi, 1));
        mx_hi = fmaxf(mx_hi, __shfl_xor_sync(0xffffffffu, mx_hi, 2));
        if (tg == 0) { redmax[wn][rlo] = mx_lo; redmax[wn][rhi] = mx_hi; }
        __syncthreads();

        float cm_lo = fmaxf(fmaxf(redmax[0][rlo], redmax[1][rlo]),
                            fmaxf(redmax[2][rlo], redmax[3][rlo]));
        float cm_hi = fmaxf(fmaxf(redmax[0][rhi], redmax[1][rhi]),
                            fmaxf(redmax[2][rhi], redmax[3][rhi]));
        float nm_lo = fmaxf(rm_lo, cm_lo), f_lo = __expf(rm_lo - nm_lo);
        float nm_hi = fmaxf(rm_hi, cm_hi), f_hi = __expf(rm_hi - nm_hi);
        rm_lo = nm_lo; rm_hi = nm_hi;

        float e[4][4];
        float sum_lo = 0.f, sum_hi = 0.f;
#pragma unroll
        for (int nt = 0; nt < 4; nt++) {
            e[nt][0] = __expf(sacc[nt][0] - nm_lo);
            e[nt][1] = __expf(sacc[nt][1] - nm_lo);
            e[nt][2] = __expf(sacc[nt][2] - nm_hi);
            e[nt][3] = __expf(sacc[nt][3] - nm_hi);
            sum_lo += e[nt][0] + e[nt][1];
            sum_hi += e[nt][2] + e[nt][3];
        }
        sum_lo += __shfl_xor_sync(0xffffffffu, sum_lo, 1);
        sum_lo += __shfl_xor_sync(0xffffffffu, sum_lo, 2);
        sum_hi += __shfl_xor_sync(0xffffffffu, sum_hi, 1);
        sum_hi += __shfl_xor_sync(0xffffffffu, sum_hi, 2);
        if (tg == 0) { redsum[wn][rlo] = sum_lo; redsum[wn][rhi] = sum_hi; }
        __syncthreads();

        rs_lo = rs_lo * f_lo + redsum[0][rlo] + redsum[1][rlo] + redsum[2][rlo] + redsum[3][rlo];
        rs_hi = rs_hi * f_hi + redsum[0][rhi] + redsum[1][rhi] + redsum[2][rhi] + redsum[3][rhi];

#pragma unroll
        for (int dn = 0; dn < 2; dn++) {
            od[dn][0] *= f_lo; od[dn][1] *= f_lo;
            od[dn][2] *= f_hi; od[dn][3] *= f_hi;
        }
        uint32_t ph[2][4], pl[2][4];
#pragma unroll
        for (int ks = 0; ks < 2; ks++) {
            pack2(e[2*ks][0],   e[2*ks][1],   ph[ks][0], pl[ks][0]);
            pack2(e[2*ks][2],   e[2*ks][3],   ph[ks][1], pl[ks][1]);
            pack2(e[2*ks+1][0], e[2*ks+1][1], ph[ks][2], pl[ks][2]);
            pack2(e[2*ks+1][2], e[2*ks+1][3], ph[ks][3], pl[ks][3]);
        }
#pragma unroll
        for (int ks = 0; ks < 2; ks++) {
#pragma unroll
            for (int dn = 0; dn < 2; dn++) {
                int vrow = dn * 8 + g;
                int kk = wn * 32 + ks * 16;
                uint32_t vb0 = *(uint32_t*)&VH[vrow * VP + kk + 2*tg];
                uint32_t vb1 = *(uint32_t*)&VH[vrow * VP + kk + 2*tg + 8];
                uint32_t vc0 = *(uint32_t*)&VL[vrow * VP + kk + 2*tg];
                uint32_t vc1 = *(uint32_t*)&VL[vrow * VP + kk + 2*tg + 8];
                mma16816(od[dn], ph[ks][0], ph[ks][1], ph[ks][2], ph[ks][3], vb0, vb1);
                mma16816(od[dn], pl[ks][0], pl[ks][1], pl[ks][2], pl[ks][3], vb0, vb1);
                mma16816(od[dn], ph[ks][0], ph[ks][1], ph[ks][2], ph[ks][3], vc0, vc1);
            }
        }
    }

#pragma unroll
    for (int dn = 0; dn < 2; dn++) {
        Of[wn][wm][g][dn*8 + 2*tg]       = od[dn][0];
        Of[wn][wm][g][dn*8 + 2*tg + 1]   = od[dn][1];
        Of[wn][wm][g+8][dn*8 + 2*tg]     = od[dn][2];
        Of[wn][wm][g+8][dn*8 + 2*tg + 1] = od[dn][3];
    }
    if (tg == 0 && wn == 0) {
        rsinv[rlo] = 1.f / rs_lo;
        rsinv[rhi] = 1.f / rs_hi;
    }
    __syncthreads();

    int q = tid & 31, dd = tid >> 5;
    float inv = rsinv[q];
    int qm = q >> 4, qr = q & 15;
    float* Ob = O + (long)b * 256 * 1024;
#pragma unroll
    for (int h2 = 0; h2 < 2; h2++) {
        int D = dd + h2 * 8;
        float v = (Of[0][qm][qr][D] + Of[1][qm][qr][D] +
                   Of[2][qm][qr][D] + Of[3][qm][qr][D]) * inv;
        Ob[(head * 64 + D * 4 + t) * 1024 + r0 + q] = v;
    }
}

// ---------------------------------------------------------------------------
// PE conv + residual; emits bf16 hi/lo split planes (R14, unchanged)
// ---------------------------------------------------------------------------
__global__ void pe_kernel(const float* __restrict__ I, const float* __restrict__ pw,
                          const float* __restrict__ pb,
                          __nv_bfloat16* __restrict__ H, __nv_bfloat16* __restrict__ L,
                          long bsP) {
    int idx = blockIdx.x * 256 + threadIdx.x;
    if (idx >= 4 * 256 * 1024) return;
    int p = idx & 1023;
    int m = (idx >> 10) & 255;
    int b = idx >> 18;
    int h = p >> 5, w = p & 31;
    int co = m >> 2, t = m & 3, g = co >> 2;
    const float* Ib = I + (long)b * 256 * 1024;
    float acc = Ib[m * 1024 + p] + pb[m];
#pragma unroll
    for (int s = 0; s < 4; s++) {
        float sg = c_sgn[t * 4 + s];
        const float* wc = pw + ((long)c_cmp[t * 4 + s] * 64 + co) * 36;
#pragma unroll
        for (int cil = 0; cil < 4; cil++) {
            const float* in = Ib + ((g * 4 + cil) * 4 + s) * 1024;
            const float* wk = wc + cil * 9;
            float part = 0.f;
#pragma unroll
            for (int kh = 0; kh < 3; kh++) {
                int hh = h + kh - 1;
                if (hh < 0 || hh > 31) continue;
#pragma unroll
                for (int kw = 0; kw < 3; kw++) {
                    int ww = w + kw - 1;
                    if (ww < 0 || ww > 31) continue;
                    part += in[hh * 32 + ww] * wk[kh * 3 + kw];
                }
            }
            acc += sg * part;
        }
    }
    __nv_bfloat16 hh, ll;
    splitf(acc, hh, ll);
    long o = (long)b * bsP + (long)m * 1024 + p;
    H[o] = hh;
    L[o] = ll;
}

// ---------------------------------------------------------------------------
extern "C" void kernel_launch(void* const* d_in, const int* in_sizes, int n_in,
                              void* d_out, int out_size) {
    const float* x      = (const float*)d_in[0];
    const float* cv1_w  = (const float*)d_in[1];
    const float* bn1_g  = (const float*)d_in[2];
    const float* bn1_b  = (const float*)d_in[3];
    const float* qkv_w  = (const float*)d_in[4];
    const float* qkv_b  = (const float*)d_in[5];
    const float* proj_w = (const float*)d_in[6];
    const float* proj_b = (const float*)d_in[7];
    const float* pe_w   = (const float*)d_in[8];
    const float* pe_b   = (const float*)d_in[9];
    const float* ang    = (const float*)d_in[10];
    const float* anb    = (const float*)d_in[11];
    const float* f1w    = (const float*)d_in[12];
    const float* f1g    = (const float*)d_in[13];
    const float* f1b    = (const float*)d_in[14];
    const float* f2w    = (const float*)d_in[15];
    const float* f2g    = (const float*)d_in[16];
    const float* f2b    = (const float*)d_in[17];
    const float* cv2_w  = (const float*)d_in[18];
    const float* bn2_g  = (const float*)d_in[19];
    const float* bn2_b  = (const float*)d_in[20];

    float *buf1, *buf2, *buf3;
    __nv_bfloat16 *xh0, *xl0, *xh1, *xl1, *Wh, *Wl;
    cudaGetSymbolAddress((void**)&buf1, g_buf1);
    cudaGetSymbolAddress((void**)&buf2, g_buf2);
    cudaGetSymbolAddress((void**)&buf3, g_buf3);
    cudaGetSymbolAddress((void**)&xh0,  g_xh0);
    cudaGetSymbolAddress((void**)&xl0,  g_xl0);
    cudaGetSymbolAddress((void**)&xh1,  g_xh1);
    cudaGetSymbolAddress((void**)&xl1,  g_xl1);
    cudaGetSymbolAddress((void**)&Wh,   g_Wh);
    cudaGetSymbolAddress((void**)&Wl,   g_Wl);

    const long S512 = 512L * 1024, S768 = 768L * 1024, S256 = 256L * 1024;

    cudaFuncSetAttribute(mma_gemm_kernel,
                         cudaFuncAttributeMaxDynamicSharedMemorySize, GEMM_SMEM);
    cudaFuncSetAttribute(mma_gemm_m32,
                         cudaFuncAttributeMaxDynamicSharedMemorySize, GEMM2_SMEM);

    expand_all_kernel<<<dim3(32, 6), 256>>>(cv1_w, qkv_w, proj_w, f1w, f2w, cv2_w, Wh, Wl);
    split_x_kernel<<<2048, 256>>>(x, xh0, xl0);

    // dummy: shifts ncu capture slot onto the cv1 GEMM below
    dummy_kernel<<<1, 32>>>();

    // cv1 + iqbn(+relu) -> P1 (512 rows)
    mma_gemm_kernel<<<dim3(8, 8, 4), 128, GEMM_SMEM>>>(Wh + OFF_W1, Wl + OFF_W1, xh0, xl0,
                                                        buf1, nullptr, 512, 512, S512, S512);
    bn_fused_split<<<512, 256>>>(buf1, xh1, xl1, bn1_g, bn1_b, S512, S512, 1);

    // qkv
    mma_gemm_kernel<<<dim3(8, 12, 4), 128, GEMM_SMEM>>>(Wh + OFF_WQ, Wl + OFF_WQ, xh1, xl1,
                                                         buf2, qkv_b, 768, 256, S512, S768);

    // attention (tensor cores)
    attn_kernel<<<dim3(32, 16, 4), 256>>>(buf2, buf3);

    // pe conv + residual -> P0
    pe_kernel<<<4096, 256>>>(buf3, pe_w, pe_b, xh0, xl0, S512);

    // proj + attn_norm -> P0 (small-M variant: 256 CTAs, full SM coverage)
    mma_gemm_m32<<<dim3(8, 8, 4), 128, GEMM2_SMEM>>>(Wh + OFF_WP, Wl + OFF_WP, xh0, xl0,
                                                      buf3, proj_b, 256, 256, S512, S256);
    bn_fused_split<<<256, 256>>>(buf3, xh0, xl0, ang, anb, S256, S512, 0);

    // ffn1 + bn(+relu) -> P0
    mma_gemm_kernel<<<dim3(8, 8, 4), 128, GEMM_SMEM>>>(Wh + OFF_F1, Wl + OFF_F1, xh0, xl0,
                                                        buf2, nullptr, 512, 256, S512, S512);
    bn_fused_split<<<512, 256>>>(buf2, xh0, xl0, f1g, f1b, S512, S512, 1);

    // ffn2 + bn -> P1 rows 0..255 (small-M variant)
    mma_gemm_m32<<<dim3(8, 8, 4), 128, GEMM2_SMEM>>>(Wh + OFF_F2, Wl + OFF_F2, xh0, xl0,
                                                      buf3, nullptr, 256, 512, S512, S256);
    bn_fused_split<<<256, 256>>>(buf3, xh1, xl1, f2g, f2b, S256, S512, 0);

    // cv2 on concat + bn + relu -> d_out
    mma_gemm_kernel<<<dim3(8, 8, 4), 128, GEMM_SMEM>>>(Wh + OFF_C2, Wl + OFF_C2, xh1, xl1,
                                                        buf2, nullptr, 512, 512, S512, S512);
    bn_fused_out<<<512, 256>>>(buf2, (float*)d_out, bn2_g, bn2_b, S512, S512, 1);
}

// round 16
// speedup vs baseline: 1.0074x; 1.0074x over previous
#include <cuda_runtime.h>
#include <cuda_bf16.h>
#include <cstdint>

// ---------------------------------------------------------------------------
// Quaternion Hamilton-product tables
// ---------------------------------------------------------------------------
__constant__ int   c_cmp[16] = {0,1,2,3,  1,0,3,2,  2,3,0,1,  3,2,1,0};
__constant__ float c_sgn[16] = {1.f,-1.f,-1.f,-1.f,
                                1.f, 1.f, 1.f,-1.f,
                                1.f,-1.f, 1.f, 1.f,
                                1.f, 1.f,-1.f, 1.f};

// ---------------------------------------------------------------------------
// Scratch (device globals)
// ---------------------------------------------------------------------------
__device__ float g_buf1[4*512*1024];
__device__ float g_buf2[4*768*1024];
__device__ float g_buf3[4*256*1024];
__device__ __align__(16) __nv_bfloat16 g_xh0[4*512*1024];
__device__ __align__(16) __nv_bfloat16 g_xl0[4*512*1024];
__device__ __align__(16) __nv_bfloat16 g_xh1[4*512*1024];
__device__ __align__(16) __nv_bfloat16 g_xl1[4*512*1024];
__device__ __align__(16) __nv_bfloat16 g_Wh[1048576];
__device__ __align__(16) __nv_bfloat16 g_Wl[1048576];

#define OFF_W1 0
#define OFF_WQ (OFF_W1 + 512*512)
#define OFF_WP (OFF_WQ + 768*256)
#define OFF_F1 (OFF_WP + 256*256)
#define OFF_F2 (OFF_F1 + 512*256)
#define OFF_C2 (OFF_F2 + 256*512)

__device__ __forceinline__ void splitf(float v, __nv_bfloat16& h, __nv_bfloat16& l) {
    h = __float2bfloat16(v);
    l = __float2bfloat16(v - __bfloat162float(h));
}

// Paired split via cvt.rn.bf16x2 — bit-identical to two splitf calls.
__device__ __forceinline__ uint32_t cvt2(float hi, float lo) {
    uint32_t d;
    asm("cvt.rn.bf16x2.f32 %0, %1, %2;" : "=r"(d) : "f"(hi), "f"(lo));
    return d;
}
__device__ __forceinline__ void pack2(float x, float y, uint32_t& h, uint32_t& l) {
    h = cvt2(y, x);
    float hx = __uint_as_float(h << 16);
    float hy = __uint_as_float(h & 0xFFFF0000u);
    l = cvt2(y - hy, x - hx);
}

// ---------------------------------------------------------------------------
// Fused expansion: quaternion weights -> dense bf16 hi/lo GEMM weights
// ---------------------------------------------------------------------------
__global__ void expand_all_kernel(const float* __restrict__ w0, const float* __restrict__ w1,
                                  const float* __restrict__ w2, const float* __restrict__ w3,
                                  const float* __restrict__ w4, const float* __restrict__ w5,
                                  __nv_bfloat16* __restrict__ Wh, __nv_bfloat16* __restrict__ Wl) {
    const int Couts[6] = {128,192,64,128,64,128};
    const int Cins [6] = {128, 64,64, 64,128,128};
    const int offs [6] = {OFF_W1,OFF_WQ,OFF_WP,OFF_F1,OFF_F2,OFF_C2};
    const float* srcs[6] = {w0,w1,w2,w3,w4,w5};
    int q = blockIdx.y;
    int Cout = Couts[q], Cin = Cins[q];
    const float* w = srcs[q];
    int off = offs[q];
    int total = 16 * Cout * Cin;
    for (int i = blockIdx.x * blockDim.x + threadIdx.x; i < total;
         i += gridDim.x * blockDim.x) {
        int s = i & 3, t = (i >> 2) & 3;
        int rest = i >> 4;
        int ci = rest % Cin, co = rest / Cin;
        float val = c_sgn[t*4 + s] * w[c_cmp[t*4 + s] * Cout * Cin + co * Cin + ci];
        __nv_bfloat16 h, l;
        splitf(val, h, l);
        int idx = off + (co*4 + t) * (4*Cin) + ci*4 + s;
        Wh[idx] = h;
        Wl[idx] = l;
    }
}

// ---------------------------------------------------------------------------
// Plain fp32 -> bf16 hi/lo split (network input x)
// ---------------------------------------------------------------------------
__global__ __launch_bounds__(256) void split_x_kernel(const float* __restrict__ X,
                                                      __nv_bfloat16* __restrict__ H,
                                                      __nv_bfloat16* __restrict__ L) {
    int i = blockIdx.x * 256 + threadIdx.x;
    float4 v = ((const float4*)X)[i];
    uint32_t h01, l01, h23, l23;
    pack2(v.x, v.y, h01, l01);
    pack2(v.z, v.w, h23, l23);
    *(uint2*)(H + (long)i * 4) = make_uint2(h01, h23);
    *(uint2*)(L + (long)i * 4) = make_uint2(l01, l23);
}

// ---------------------------------------------------------------------------
// mma / ldmatrix helpers
// ---------------------------------------------------------------------------
__device__ __forceinline__ void mma16816(float* d, uint32_t a0, uint32_t a1,
                                         uint32_t a2, uint32_t a3,
                                         uint32_t b0, uint32_t b1) {
    asm volatile(
        "mma.sync.aligned.m16n8k16.row.col.f32.bf16.bf16.f32 "
        "{%0,%1,%2,%3}, {%4,%5,%6,%7}, {%8,%9}, {%0,%1,%2,%3};"
        : "+f"(d[0]), "+f"(d[1]), "+f"(d[2]), "+f"(d[3])
        : "r"(a0), "r"(a1), "r"(a2), "r"(a3), "r"(b0), "r"(b1));
}
__device__ __forceinline__ void ldsm4(uint32_t& r0, uint32_t& r1, uint32_t& r2,
                                      uint32_t& r3, uint32_t addr) {
    asm volatile("ldmatrix.sync.aligned.m8n8.x4.shared.b16 {%0,%1,%2,%3}, [%4];"
                 : "=r"(r0), "=r"(r1), "=r"(r2), "=r"(r3) : "r"(addr));
}
__device__ __forceinline__ void ldsm4t(uint32_t& r0, uint32_t& r1, uint32_t& r2,
                                       uint32_t& r3, uint32_t addr) {
    asm volatile("ldmatrix.sync.aligned.m8n8.x4.trans.shared.b16 {%0,%1,%2,%3}, [%4];"
                 : "=r"(r0), "=r"(r1), "=r"(r2), "=r"(r3) : "r"(addr));
}

// ---------------------------------------------------------------------------
// HMMA bf16-split GEMM. CTA tile 64m x 128n, 4 warps, K-chunk 32,
// double-buffered. B staging now uint4-granular (half the LSU issue slots
// vs R14's uint2 scheme; same bytes, same layout, same addresses).
// ---------------------------------------------------------------------------
#define APITCH 40
#define BPITCH 136
#define A_PLANE (64*APITCH)
#define B_PLANE (32*BPITCH)
#define GBUF (2*A_PLANE + 2*B_PLANE)
#define GEMM_SMEM (2*GBUF*2)

__global__ __launch_bounds__(128) void mma_gemm_kernel(
    const __nv_bfloat16* __restrict__ Wh, const __nv_bfloat16* __restrict__ Wl,
    const __nv_bfloat16* __restrict__ Xh, const __nv_bfloat16* __restrict__ Xl,
    float* __restrict__ Y, const float* __restrict__ bias,
    int M, int K, long sX, long sY)
{
    extern __shared__ __nv_bfloat16 smd[];
    const uint32_t smem_base = (uint32_t)__cvta_generic_to_shared(smd);

    const int tid = threadIdx.x;
    const int wid = tid >> 5, lane = tid & 31;
    const int wm = wid & 1, wn = wid >> 1;
    const int g = lane >> 2, tg = lane & 3;
    const int mo = blockIdx.y * 64, no = blockIdx.x * 128;
    const __nv_bfloat16* Xhb = Xh + blockIdx.z * sX;
    const __nv_bfloat16* Xlb = Xl + blockIdx.z * sX;
    float* Yb = Y + blockIdx.z * sY;

    const int am = tid >> 1, ak = (tid & 1) * 16;
    // B loader: uint4 units. thread -> col8 = (tid&15)*8, rows brow+8j (j=0..3)
    const int bcol8 = (tid & 15) * 8;
    const int brow  = tid >> 4;

    float acc[2][8][4] = {};
    const int nch = K >> 5;

    uint4 awh[2], awl[2];
    uint4 b4h[4], b4l[4];

#define LOAD_REGS(kt)                                                            \
    {                                                                            \
        const __nv_bfloat16* Ah = Wh + (long)(mo + am) * K + (kt) + ak;          \
        const __nv_bfloat16* Al = Wl + (long)(mo + am) * K + (kt) + ak;          \
        awh[0] = *(const uint4*)Ah; awh[1] = *(const uint4*)(Ah + 8);            \
        awl[0] = *(const uint4*)Al; awl[1] = *(const uint4*)(Al + 8);            \
        _Pragma("unroll")                                                        \
        for (int I = 0; I < 4; I++) {                                            \
            int kr = (kt) + brow + 8 * I;                                        \
            b4h[I] = *(const uint4*)(Xhb + (long)kr * 1024 + no + bcol8);        \
            b4l[I] = *(const uint4*)(Xlb + (long)kr * 1024 + no + bcol8);        \
        }                                                                        \
    }

#define STORE_SMEM(buf)                                                          \
    {                                                                            \
        __nv_bfloat16* base = smd + (buf) * GBUF;                                \
        uint32_t* dH = (uint32_t*)(base + am * APITCH + ak);                     \
        uint32_t* dL = (uint32_t*)(base + A_PLANE + am * APITCH + ak);           \
        *(uint4*)dH = awh[0]; *(uint4*)(dH + 4) = awh[1];                        \
        *(uint4*)dL = awl[0]; *(uint4*)(dL + 4) = awl[1];                        \
        __nv_bfloat16* BH = base + 2 * A_PLANE;                                  \
        __nv_bfloat16* BL = base + 2 * A_PLANE + B_PLANE;                        \
        _Pragma("unroll")                                                        \
        for (int I = 0; I < 4; I++) {                                            \
            int kr = brow + 8 * I;                                               \
            *(uint4*)(BH + kr * BPITCH + bcol8) = b4h[I];                        \
            *(uint4*)(BL + kr * BPITCH + bcol8) = b4l[I];                        \
        }                                                                        \
    }

    LOAD_REGS(0);
    STORE_SMEM(0);
    if (nch > 1) LOAD_REGS(32);
    __syncthreads();

    const int a_row_l = lane & 15;
    const int a_khalf = (lane >> 4) * 8;
    const int b_krow  = (lane & 7) + 8 * ((lane >> 3) & 1);
    const int b_nhalf = (lane >> 4) * 8;

    for (int ch = 0; ch < nch; ch++) {
        if (ch + 1 < nch) STORE_SMEM((ch + 1) & 1);
        if (ch + 2 < nch) LOAD_REGS((ch + 2) * 32);

        uint32_t bufu = (uint32_t)((ch & 1) * GBUF) * 2u;
        uint32_t AH = smem_base + bufu;
        uint32_t ALo = AH + A_PLANE * 2;
        uint32_t BH = AH + 4 * A_PLANE;
        uint32_t BLo = BH + B_PLANE * 2;

#pragma unroll
        for (int k0 = 0; k0 < 32; k0 += 16) {
            uint32_t ah[2][4], al[2][4];
#pragma unroll
            for (int mt = 0; mt < 2; mt++) {
                int rowb = wm * 32 + mt * 16;
                uint32_t off = (uint32_t)((rowb + a_row_l) * APITCH + k0 + a_khalf) * 2u;
                ldsm4(ah[mt][0], ah[mt][1], ah[mt][2], ah[mt][3], AH + off);
                ldsm4(al[mt][0], al[mt][1], al[mt][2], al[mt][3], ALo + off);
            }
#pragma unroll
            for (int ntp = 0; ntp < 4; ntp++) {
                int nbase = wn * 64 + ntp * 16;
                uint32_t off = (uint32_t)((k0 + b_krow) * BPITCH + nbase + b_nhalf) * 2u;
                uint32_t bh0, bh1, bh2, bh3, bl0, bl1, bl2, bl3;
                ldsm4t(bh0, bh1, bh2, bh3, BH + off);
                ldsm4t(bl0, bl1, bl2, bl3, BLo + off);
#pragma unroll
                for (int mt = 0; mt < 2; mt++) {
                    float* d0 = acc[mt][ntp * 2];
                    float* d1 = acc[mt][ntp * 2 + 1];
                    mma16816(d0, ah[mt][0], ah[mt][1], ah[mt][2], ah[mt][3], bh0, bh1);
                    mma16816(d0, al[mt][0], al[mt][1], al[mt][2], al[mt][3], bh0, bh1);
                    mma16816(d0, ah[mt][0], ah[mt][1], ah[mt][2], ah[mt][3], bl0, bl1);
                    mma16816(d1, ah[mt][0], ah[mt][1], ah[mt][2], ah[mt][3], bh2, bh3);
                    mma16816(d1, al[mt][0], al[mt][1], al[mt][2], al[mt][3], bh2, bh3);
                    mma16816(d1, ah[mt][0], ah[mt][1], ah[mt][2], ah[mt][3], bl2, bl3);
                }
            }
        }
        if (ch + 1 < nch) __syncthreads();
    }

#pragma unroll
    for (int mt = 0; mt < 2; mt++) {
        int r0 = mo + wm * 32 + mt * 16 + g;
        int r1 = r0 + 8;
        float bv0 = bias ? bias[r0] : 0.f;
        float bv1 = bias ? bias[r1] : 0.f;
#pragma unroll
        for (int nt = 0; nt < 8; nt++) {
            int c = no + wn * 64 + nt * 8 + 2 * tg;
            float* d = acc[mt][nt];
            *(float2*)(Yb + (long)r0 * 1024 + c) = make_float2(d[0] + bv0, d[1] + bv0);
            *(float2*)(Yb + (long)r1 * 1024 + c) = make_float2(d[2] + bv1, d[3] + bv1);
        }
    }
#undef LOAD_REGS
#undef STORE_SMEM
}

// ---------------------------------------------------------------------------
// Fused BN: stats + apply + bf16 split (R14, unchanged)
// ---------------------------------------------------------------------------
__global__ __launch_bounds__(256) void bn_fused_split(
    const float* __restrict__ X, __nv_bfloat16* __restrict__ H,
    __nv_bfloat16* __restrict__ L,
    const float* __restrict__ g, const float* __restrict__ be,
    long bsX, long bsP, int relu)
{
    int m = blockIdx.x, tid = threadIdx.x;
    float4 v[4];
    float s = 0.f, sq = 0.f;
#pragma unroll
    for (int b = 0; b < 4; b++) {
        v[b] = *(const float4*)(X + b * bsX + (long)m * 1024 + tid * 4);
        s  += v[b].x + v[b].y + v[b].z + v[b].w;
        sq += v[b].x*v[b].x + v[b].y*v[b].y + v[b].z*v[b].z + v[b].w*v[b].w;
    }
#pragma unroll
    for (int o = 16; o; o >>= 1) {
        s  += __shfl_xor_sync(0xffffffffu, s, o);
        sq += __shfl_xor_sync(0xffffffffu, sq, o);
    }
    __shared__ float ps[8], pq[8], bsc[1], bsh[1];
    if ((tid & 31) == 0) { ps[tid >> 5] = s; pq[tid >> 5] = sq; }
    __syncthreads();
    if (tid == 0) {
        s = 0.f; sq = 0.f;
#pragma unroll
        for (int i = 0; i < 8; i++) { s += ps[i]; sq += pq[i]; }
        float mean = s * (1.f / 4096.f);
        float var  = sq * (1.f / 4096.f) - mean * mean;
        float rstd = rsqrtf(var + 1e-5f);
        float sc = g[m] * rstd;
        bsc[0] = sc;
        bsh[0] = be[m] - mean * sc;
    }
    __syncthreads();
    float sc = bsc[0], sh = bsh[0];
#pragma unroll
    for (int b = 0; b < 4; b++) {
        float4 w = v[b];
        w.x = w.x * sc + sh; w.y = w.y * sc + sh;
        w.z = w.z * sc + sh; w.w = w.w * sc + sh;
        if (relu) {
            w.x = fmaxf(w.x, 0.f); w.y = fmaxf(w.y, 0.f);
            w.z = fmaxf(w.z, 0.f); w.w = fmaxf(w.w, 0.f);
        }
        uint32_t h01, l01, h23, l23;
        pack2(w.x, w.y, h01, l01);
        pack2(w.z, w.w, h23, l23);
        long o = (long)b * bsP + (long)m * 1024 + tid * 4;
        *(uint2*)(H + o) = make_uint2(h01, h23);
        *(uint2*)(L + o) = make_uint2(l01, l23);
    }
}

__global__ __launch_bounds__(256) void bn_fused_out(
    const float* __restrict__ X, float* __restrict__ Y,
    const float* __restrict__ g, const float* __restrict__ be,
    long bsX, long bsY, int relu)
{
    int m = blockIdx.x, tid = threadIdx.x;
    float4 v[4];
    float s = 0.f, sq = 0.f;
#pragma unroll
    for (int b = 0; b < 4; b++) {
        v[b] = *(const float4*)(X + b * bsX + (long)m * 1024 + tid * 4);
        s  += v[b].x + v[b].y + v[b].z + v[b].w;
        sq += v[b].x*v[b].x + v[b].y*v[b].y + v[b].z*v[b].z + v[b].w*v[b].w;
    }
#pragma unroll
    for (int o = 16; o; o >>= 1) {
        s  += __shfl_xor_sync(0xffffffffu, s, o);
        sq += __shfl_xor_sync(0xffffffffu, sq, o);
    }
    __shared__ float ps[8], pq[8], bsc[1], bsh[1];
    if ((tid & 31) == 0) { ps[tid >> 5] = s; pq[tid >> 5] = sq; }
    __syncthreads();
    if (tid == 0) {
        s = 0.f; sq = 0.f;
#pragma unroll
        for (int i = 0; i < 8; i++) { s += ps[i]; sq += pq[i]; }
        float mean = s * (1.f / 4096.f);
        float var  = sq * (1.f / 4096.f) - mean * mean;
        float rstd = rsqrtf(var + 1e-5f);
        float sc = g[m] * rstd;
        bsc[0] = sc;
        bsh[0] = be[m] - mean * sc;
    }
    __syncthreads();
    float sc = bsc[0], sh = bsh[0];
#pragma unroll
    for (int b = 0; b < 4; b++) {
        float4 w = v[b];
        w.x = w.x * sc + sh; w.y = w.y * sc + sh;
        w.z = w.z * sc + sh; w.w = w.w * sc + sh;
        if (relu) {
            w.x = fmaxf(w.x, 0.f); w.y = fmaxf(w.y, 0.f);
            w.z = fmaxf(w.z, 0.f); w.w = fmaxf(w.w, 0.f);
        }
        *(float4*)(Y + (long)b * bsY + (long)m * 1024 + tid * 4) = w;
    }
}

// ---------------------------------------------------------------------------
// Tensor-core flash attention (R14, unchanged)
// ---------------------------------------------------------------------------
#define QP 24
#define KP 24
#define VP 136

__global__ __launch_bounds__(256) void attn_kernel(const float* __restrict__ Yq,
                                                   float* __restrict__ O) {
    __shared__ __nv_bfloat16 QH[32*QP], QL[32*QP];
    __shared__ __nv_bfloat16 KH[128*KP], KL[128*KP];
    __shared__ __nv_bfloat16 VH[16*VP], VL[16*VP];
    __shared__ float redmax[4][32], redsum[4][32];
    __shared__ float Of[4][2][16][17];
    __shared__ float rsinv[32];

    int b = blockIdx.z, head = blockIdx.y >> 2, t = blockIdx.y & 3;
    int r0 = blockIdx.x * 32;
    const float* Yb = Yq + (long)b * 768 * 1024;
    int tid = threadIdx.x, lane = tid & 31, wid = tid >> 5;
    int wm = wid & 1, wn = wid >> 1;
    int g = lane >> 2, tg = lane & 3;

    for (int i = tid; i < 512; i += 256) {
        int dd = i >> 5, q = i & 31;
        float v = Yb[(head * 192 + dd * 4 + t) * 1024 + r0 + q];
        __nv_bfloat16 h, l; splitf(v, h, l);
        QH[q * QP + dd] = h;
        QL[q * QP + dd] = l;
    }
    __syncthreads();

    uint32_t qh[4], ql[4];
    {
        int r = wm * 16 + g;
        qh[0] = *(uint32_t*)&QH[r * QP + 2*tg];
        qh[1] = *(uint32_t*)&QH[(r + 8) * QP + 2*tg];
        qh[2] = *(uint32_t*)&QH[r * QP + 2*tg + 8];
        qh[3] = *(uint32_t*)&QH[(r + 8) * QP + 2*tg + 8];
        ql[0] = *(uint32_t*)&QL[r * QP + 2*tg];
        ql[1] = *(uint32_t*)&QL[(r + 8) * QP + 2*tg];
        ql[2] = *(uint32_t*)&QL[r * QP + 2*tg + 8];
        ql[3] = *(uint32_t*)&QL[(r + 8) * QP + 2*tg + 8];
    }

    float od[2][4] = {};
    float rm_lo = -1e30f, rm_hi = -1e30f, rs_lo = 0.f, rs_hi = 0.f;
    const float sc = 0.25f;
    const int rlo = wm * 16 + g, rhi = rlo + 8;

    for (int ch = 0; ch < 8; ch++) {
        __syncthreads();
        for (int i = tid; i < 2048; i += 256) {
            int dd = i >> 7, key = i & 127;
            float kval = Yb[(head * 192 + 64 + dd * 4 + t) * 1024 + ch * 128 + key];
            __nv_bfloat16 h, l; splitf(kval, h, l);
            KH[key * KP + dd] = h; KL[key * KP + dd] = l;
            float vval = Yb[(head * 192 + 128 + dd * 4 + t) * 1024 + ch * 128 + key];
            splitf(vval, h, l);
            VH[dd * VP + key] = h; VL[dd * VP + key] = l;
        }
        __syncthreads();

        float sacc[4][4] = {};
#pragma unroll
        for (int nt = 0; nt < 4; nt++) {
            int nb = wn * 32 + nt * 8 + g;
            uint32_t kb0 = *(uint32_t*)&KH[nb * KP + 2*tg];
            uint32_t kb1 = *(uint32_t*)&KH[nb * KP + 2*tg + 8];
            uint32_t kc0 = *(uint32_t*)&KL[nb * KP + 2*tg];
            uint32_t kc1 = *(uint32_t*)&KL[nb * KP + 2*tg + 8];
            mma16816(sacc[nt], qh[0], qh[1], qh[2], qh[3], kb0, kb1);
            mma16816(sacc[nt], ql[0], ql[1], ql[2], ql[3], kb0, kb1);
            mma16816(sacc[nt], qh[0], qh[1], qh[2], qh[3], kc0, kc1);
        }
        float mx_lo = -1e30f, mx_hi = -1e30f;
#pragma unroll
        for (int nt = 0; nt < 4; nt++) {
            sacc[nt][0] *= sc; sacc[nt][1] *= sc;
            sacc[nt][2] *= sc; sacc[nt][3] *= sc;
            mx_lo = fmaxf(mx_lo, fmaxf(sacc[nt][0], sacc[nt][1]));
            mx_hi = fmaxf(mx_hi, fmaxf(sacc[nt][2], sacc[nt][3]));
        }
        mx_lo = fmaxf(mx_lo, __shfl_xor_sync(0xffffffffu, mx_lo, 1));
        mx_lo = fmaxf(mx_lo, __shfl_xor_sync(0xffffffffu, mx_lo, 2));
        mx_hi = fmaxf(mx_hi, __shfl_xor_sync(0xffffffffu, mx_hi, 1));
        mx_hi = fmaxf(mx_hi, __shfl_xor_sync(0xffffffffu, mx_hi, 2));
        if (tg == 0) { redmax[wn][rlo] = mx_lo; redmax[wn][rhi] = mx_hi; }
        __syncthreads();

        float cm_lo = fmaxf(fmaxf(redmax[0][rlo], redmax[1][rlo]),
                            fmaxf(redmax[2][rlo], redmax[3][rlo]));
        float cm_hi = fmaxf(fmaxf(redmax[0][rhi], redmax[1][rhi]),
                            fmaxf(redmax[2][rhi], redmax[3][rhi]));
        float nm_lo = fmaxf(rm_lo, cm_lo), f_lo = __expf(rm_lo - nm_lo);
        float nm_hi = fmaxf(rm_hi, cm_hi), f_hi = __expf(rm_hi - nm_hi);
        rm_lo = nm_lo; rm_hi = nm_hi;

        float e[4][4];
        float sum_lo = 0.f, sum_hi = 0.f;
#pragma unroll
        for (int nt = 0; nt < 4; nt++) {
            e[nt][0] = __expf(sacc[nt][0] - nm_lo);
            e[nt][1] = __expf(sacc[nt][1] - nm_lo);
            e[nt][2] = __expf(sacc[nt][2] - nm_hi);
            e[nt][3] = __expf(sacc[nt][3] - nm_hi);
            sum_lo += e[nt][0] + e[nt][1];
            sum_hi += e[nt][2] + e[nt][3];
        }
        sum_lo += __shfl_xor_sync(0xffffffffu, sum_lo, 1);
        sum_lo += __shfl_xor_sync(0xffffffffu, sum_lo, 2);
        sum_hi += __shfl_xor_sync(0xffffffffu, sum_hi, 1);
        sum_hi += __shfl_xor_sync(0xffffffffu, sum_hi, 2);
        if (tg == 0) { redsum[wn][rlo] = sum_lo; redsum[wn][rhi] = sum_hi; }
        __syncthreads();

        rs_lo = rs_lo * f_lo + redsum[0][rlo] + redsum[1][rlo] + redsum[2][rlo] + redsum[3][rlo];
        rs_hi = rs_hi * f_hi + redsum[0][rhi] + redsum[1][rhi] + redsum[2][rhi] + redsum[3][rhi];

#pragma unroll
        for (int dn = 0; dn < 2; dn++) {
            od[dn][0] *= f_lo; od[dn][1] *= f_lo;
            od[dn][2] *= f_hi; od[dn][3] *= f_hi;
        }
        uint32_t ph[2][4], pl[2][4];
#pragma unroll
        for (int ks = 0; ks < 2; ks++) {
            pack2(e[2*ks][0],   e[2*ks][1],   ph[ks][0], pl[ks][0]);
            pack2(e[2*ks][2],   e[2*ks][3],   ph[ks][1], pl[ks][1]);
            pack2(e[2*ks+1][0], e[2*ks+1][1], ph[ks][2], pl[ks][2]);
            pack2(e[2*ks+1][2], e[2*ks+1][3], ph[ks][3], pl[ks][3]);
        }
#pragma unroll
        for (int ks = 0; ks < 2; ks++) {
#pragma unroll
            for (int dn = 0; dn < 2; dn++) {
                int vrow = dn * 8 + g;
                int kk = wn * 32 + ks * 16;
                uint32_t vb0 = *(uint32_t*)&VH[vrow * VP + kk + 2*tg];
                uint32_t vb1 = *(uint32_t*)&VH[vrow * VP + kk + 2*tg + 8];
                uint32_t vc0 = *(uint32_t*)&VL[vrow * VP + kk + 2*tg];
                uint32_t vc1 = *(uint32_t*)&VL[vrow * VP + kk + 2*tg + 8];
                mma16816(od[dn], ph[ks][0], ph[ks][1], ph[ks][2], ph[ks][3], vb0, vb1);
                mma16816(od[dn], pl[ks][0], pl[ks][1], pl[ks][2], pl[ks][3], vb0, vb1);
                mma16816(od[dn], ph[ks][0], ph[ks][1], ph[ks][2], ph[ks][3], vc0, vc1);
            }
        }
    }

#pragma unroll
    for (int dn = 0; dn < 2; dn++) {
        Of[wn][wm][g][dn*8 + 2*tg]       = od[dn][0];
        Of[wn][wm][g][dn*8 + 2*tg + 1]   = od[dn][1];
        Of[wn][wm][g+8][dn*8 + 2*tg]     = od[dn][2];
        Of[wn][wm][g+8][dn*8 + 2*tg + 1] = od[dn][3];
    }
    if (tg == 0 && wn == 0) {
        rsinv[rlo] = 1.f / rs_lo;
        rsinv[rhi] = 1.f / rs_hi;
    }
    __syncthreads();

    int q = tid & 31, dd = tid >> 5;
    float inv = rsinv[q];
    int qm = q >> 4, qr = q & 15;
    float* Ob = O + (long)b * 256 * 1024;
#pragma unroll
    for (int h2 = 0; h2 < 2; h2++) {
        int D = dd + h2 * 8;
        float v = (Of[0][qm][qr][D] + Of[1][qm][qr][D] +
                   Of[2][qm][qr][D] + Of[3][qm][qr][D]) * inv;
        Ob[(head * 64 + D * 4 + t) * 1024 + r0 + q] = v;
    }
}

// ---------------------------------------------------------------------------
// PE conv + residual; emits bf16 hi/lo split planes (R14, unchanged)
// ---------------------------------------------------------------------------
__global__ void pe_kernel(const float* __restrict__ I, const float* __restrict__ pw,
                          const float* __restrict__ pb,
                          __nv_bfloat16* __restrict__ H, __nv_bfloat16* __restrict__ L,
                          long bsP) {
    int idx = blockIdx.x * 256 + threadIdx.x;
    if (idx >= 4 * 256 * 1024) return;
    int p = idx & 1023;
    int m = (idx >> 10) & 255;
    int b = idx >> 18;
    int h = p >> 5, w = p & 31;
    int co = m >> 2, t = m & 3, g = co >> 2;
    const float* Ib = I + (long)b * 256 * 1024;
    float acc = Ib[m * 1024 + p] + pb[m];
#pragma unroll
    for (int s = 0; s < 4; s++) {
        float sg = c_sgn[t * 4 + s];
        const float* wc = pw + ((long)c_cmp[t * 4 + s] * 64 + co) * 36;
#pragma unroll
        for (int cil = 0; cil < 4; cil++) {
            const float* in = Ib + ((g * 4 + cil) * 4 + s) * 1024;
            const float* wk = wc + cil * 9;
            float part = 0.f;
#pragma unroll
            for (int kh = 0; kh < 3; kh++) {
                int hh = h + kh - 1;
                if (hh < 0 || hh > 31) continue;
#pragma unroll
                for (int kw = 0; kw < 3; kw++) {
                    int ww = w + kw - 1;
                    if (ww < 0 || ww > 31) continue;
                    part += in[hh * 32 + ww] * wk[kh * 3 + kw];
                }
            }
            acc += sg * part;
        }
    }
    __nv_bfloat16 hh, ll;
    splitf(acc, hh, ll);
    long o = (long)b * bsP + (long)m * 1024 + p;
    H[o] = hh;
    L[o] = ll;
}

// ---------------------------------------------------------------------------
extern "C" void kernel_launch(void* const* d_in, const int* in_sizes, int n_in,
                              void* d_out, int out_size) {
    const float* x      = (const float*)d_in[0];
    const float* cv1_w  = (const float*)d_in[1];
    const float* bn1_g  = (const float*)d_in[2];
    const float* bn1_b  = (const float*)d_in[3];
    const float* qkv_w  = (const float*)d_in[4];
    const float* qkv_b  = (const float*)d_in[5];
    const float* proj_w = (const float*)d_in[6];
    const float* proj_b = (const float*)d_in[7];
    const float* pe_w   = (const float*)d_in[8];
    const float* pe_b   = (const float*)d_in[9];
    const float* ang    = (const float*)d_in[10];
    const float* anb    = (const float*)d_in[11];
    const float* f1w    = (const float*)d_in[12];
    const float* f1g    = (const float*)d_in[13];
    const float* f1b    = (const float*)d_in[14];
    const float* f2w    = (const float*)d_in[15];
    const float* f2g    = (const float*)d_in[16];
    const float* f2b    = (const float*)d_in[17];
    const float* cv2_w  = (const float*)d_in[18];
    const float* bn2_g  = (const float*)d_in[19];
    const float* bn2_b  = (const float*)d_in[20];

    float *buf1, *buf2, *buf3;
    __nv_bfloat16 *xh0, *xl0, *xh1, *xl1, *Wh, *Wl;
    cudaGetSymbolAddress((void**)&buf1, g_buf1);
    cudaGetSymbolAddress((void**)&buf2, g_buf2);
    cudaGetSymbolAddress((void**)&buf3, g_buf3);
    cudaGetSymbolAddress((void**)&xh0,  g_xh0);
    cudaGetSymbolAddress((void**)&xl0,  g_xl0);
    cudaGetSymbolAddress((void**)&xh1,  g_xh1);
    cudaGetSymbolAddress((void**)&xl1,  g_xl1);
    cudaGetSymbolAddress((void**)&Wh,   g_Wh);
    cudaGetSymbolAddress((void**)&Wl,   g_Wl);

    const long S512 = 512L * 1024, S768 = 768L * 1024, S256 = 256L * 1024;

    cudaFuncSetAttribute(mma_gemm_kernel,
                         cudaFuncAttributeMaxDynamicSharedMemorySize, GEMM_SMEM);

    expand_all_kernel<<<dim3(32, 6), 256>>>(cv1_w, qkv_w, proj_w, f1w, f2w, cv2_w, Wh, Wl);
    split_x_kernel<<<2048, 256>>>(x, xh0, xl0);

    // cv1 + iqbn(+relu) -> P1 (512 rows)
    mma_gemm_kernel<<<dim3(8, 8, 4), 128, GEMM_SMEM>>>(Wh + OFF_W1, Wl + OFF_W1, xh0, xl0,
                                                        buf1, nullptr, 512, 512, S512, S512);
    bn_fused_split<<<512, 256>>>(buf1, xh1, xl1, bn1_g, bn1_b, S512, S512, 1);

    // qkv
    mma_gemm_kernel<<<dim3(8, 12, 4), 128, GEMM_SMEM>>>(Wh + OFF_WQ, Wl + OFF_WQ, xh1, xl1,
                                                         buf2, qkv_b, 768, 256, S512, S768);

    // attention (tensor cores)
    attn_kernel<<<dim3(32, 16, 4), 256>>>(buf2, buf3);

    // pe conv + residual -> P0
    pe_kernel<<<4096, 256>>>(buf3, pe_w, pe_b, xh0, xl0, S512);

    // proj + attn_norm -> P0
    mma_gemm_kernel<<<dim3(8, 4, 4), 128, GEMM_SMEM>>>(Wh + OFF_WP, Wl + OFF_WP, xh0, xl0,
                                                        buf3, proj_b, 256, 256, S512, S256);
    bn_fused_split<<<256, 256>>>(buf3, xh0, xl0, ang, anb, S256, S512, 0);

    // ffn1 + bn(+relu) -> P0
    mma_gemm_kernel<<<dim3(8, 8, 4), 128, GEMM_SMEM>>>(Wh + OFF_F1, Wl + OFF_F1, xh0, xl0,
                                                        buf2, nullptr, 512, 256, S512, S512);
    bn_fused_split<<<512, 256>>>(buf2, xh0, xl0, f1g, f1b, S512, S512, 1);

    // ffn2 + bn -> P1 rows 0..255 (rows 256..511 = b from bn1)
    mma_gemm_kernel<<<dim3(8, 4, 4), 128, GEMM_SMEM>>>(Wh + OFF_F2, Wl + OFF_F2, xh0, xl0,
                                                        buf3, nullptr, 256, 512, S512, S256);
    bn_fused_split<<<256, 256>>>(buf3, xh1, xl1, f2g, f2b, S256, S512, 0);

    // cv2 on concat + bn + relu -> d_out
    mma_gemm_kernel<<<dim3(8, 8, 4), 128, GEMM_SMEM>>>(Wh + OFF_C2, Wl + OFF_C2, xh1, xl1,
                                                        buf2, nullptr, 512, 512, S512, S512);
    bn_fused_out<<<512, 256>>>(buf2, (float*)d_out, bn2_g, bn2_b, S512, S512, 1);
}